// round 5
// baseline (speedup 1.0000x reference)
#include <cuda_runtime.h>

// Problem constants: H=64, M=N=128, k=9, w=3
#define PTOT (64 * 128 * 128)
#define KNN  9

// Tile: 16 x 4 x 4 voxels per block; halo 18 x 6 x 6
#define TX 16
#define TY 4
#define TZ 4
#define HX 18
#define HY 6
#define HZH 6
#define HROWS (HX * HY * HZH)   // 648
#define HXY (HX * HY)           // 108

// Scratch: per-voxel 9 selected values (12-float padded row, as 3 float4)
// and 9 window codes (bytes packed in 3 u32 words).
__device__ float4       g_val4[PTOT * 3];    // 50.3 MB
__device__ unsigned int g_code32[PTOT * 3];  // 12.6 MB

// ---------------------------------------------------------------------------
// Forced-predication pair compares: exactly SETP + @P ADD + @!P ADD (3 instr).
// Semantics for pair (j < c):  if (d_j <= d_c) rank_c += wc  else rank_j += wj
// ---------------------------------------------------------------------------
__device__ __forceinline__ void cmp_i2(unsigned& rc, unsigned& rj,
                                       unsigned dj, unsigned dc,
                                       unsigned wc, unsigned wj) {
    asm("{\n\t.reg .pred p;\n\t"
        "setp.le.u32 p, %2, %3;\n\t"
        "@p  add.u32 %0, %0, %4;\n\t"
        "@!p add.u32 %1, %1, %5;\n\t}"
        : "+r"(rc), "+r"(rj)
        : "r"(dj), "r"(dc), "r"(wc), "r"(wj));
}
__device__ __forceinline__ void cmp_i1(unsigned& r,
                                       unsigned dj, unsigned dc,
                                       unsigned wc, unsigned wj) {
    asm("{\n\t.reg .pred p;\n\t.reg .u32 t;\n\t"
        "setp.le.u32 p, %1, %2;\n\t"
        "selp.u32 t, %3, %4, p;\n\t"
        "add.u32 %0, %0, t;\n\t}"
        : "+r"(r)
        : "r"(dj), "r"(dc), "r"(wc), "r"(wj));
}
__device__ __forceinline__ void cmp_f2(float& rc, float& rj,
                                       float dj, float dc,
                                       float wc, float wj) {
    asm("{\n\t.reg .pred p;\n\t"
        "setp.le.f32 p, %2, %3;\n\t"
        "@p  add.f32 %0, %0, %4;\n\t"
        "@!p add.f32 %1, %1, %5;\n\t}"
        : "+f"(rc), "+f"(rj)
        : "f"(dj), "f"(dc), "f"(wc), "f"(wj));
}

// ---------------------------------------------------------------------------
// Pass 1: stable top-9 of 27 periodic window neighbors by |v - center|.
//   rank(c) = #{j<c: d_j <= d_c} + #{j>c: d_j < d_c}
// One compare per unordered pair; pairs split between FSETP (FMA pipe) and
// ISETP-on-abs-bits (ALU pipe; identical order for d >= 0) to load both pipes
// ~50/50 at 3 issue slots/pair. Diagonal iteration rotates accumulators.
// Packed rank counters: 4 bytes per int reg, 2 fields (1 / 1024) per float reg.
// ---------------------------------------------------------------------------
__global__ __launch_bounds__(256, 4) void pass1_kernel(const float* __restrict__ anat) {
    __shared__ float        s_anat[HROWS];
    __shared__ float4       s_val[256 * 3];
    __shared__ unsigned int s_code[256 * 3];

    int tid = threadIdx.x;
    int lx = tid & 15, ly = (tid >> 4) & 3, lz = tid >> 6;
    int x0 = blockIdx.x * TX, y0 = blockIdx.y * TY, z0 = blockIdx.z * TZ;

    for (int t = tid; t < HROWS; t += 256) {
        int hx = t % HX; int r = t / HX; int hy = r % HY; int hz = r / HY;
        int gx = (x0 + hx + 127) & 127;
        int gy = (y0 + hy + 127) & 127;
        int gz = (z0 + hz + 63) & 63;
        s_anat[t] = __ldg(&anat[(gz << 14) | (gy << 7) | gx]);
    }
    __syncthreads();

    int center = (lz + 1) * HXY + (ly + 1) * HX + (lx + 1);
    float ac = s_anat[center];

    float fd[27];
#pragma unroll
    for (int oz = 0; oz < 3; ++oz)
#pragma unroll
        for (int oy = 0; oy < 3; ++oy)
#pragma unroll
            for (int ox = 0; ox < 3; ++ox) {
                int c = oz * 9 + oy * 3 + ox;
                fd[c] = fabsf(s_anat[center + (oz - 1) * HXY + (oy - 1) * HX + (ox - 1)] - ac);
            }

    unsigned ri[7];
    float    rf[14];
#pragma unroll
    for (int k = 0; k < 7;  ++k) ri[k] = 0u;
#pragma unroll
    for (int k = 0; k < 14; ++k) rf[k] = 0.0f;

    // Diagonal iteration: pair (j, c=j+o); forced 3-instr predicated bodies.
#pragma unroll
    for (int o = 1; o < 27; ++o)
#pragma unroll
        for (int j = 0; j + o < 27; ++j) {
            const int c = j + o;
            if (((j + c) & 1) == 0) {
                // float pipe; same-parity pair => c>>1 != j>>1 always
                cmp_f2(rf[c >> 1], rf[j >> 1], fd[j], fd[c],
                       (c & 1) ? 1024.0f : 1.0f, (j & 1) ? 1024.0f : 1.0f);
            } else {
                unsigned dj = __float_as_uint(fd[j]);
                unsigned dc = __float_as_uint(fd[c]);
                unsigned wc = 1u << ((c & 3) * 8);
                unsigned wj = 1u << ((j & 3) * 8);
                if ((c >> 2) == (j >> 2)) cmp_i1(ri[c >> 2], dj, dc, wc, wj);
                else                      cmp_i2(ri[c >> 2], ri[j >> 2], dj, dc, wc, wj);
            }
        }

    int fi[14];
#pragma unroll
    for (int k = 0; k < 14; ++k) fi[k] = (int)rf[k];

    float*         svf = (float*)s_val;
    unsigned char* scb = (unsigned char*)s_code;
#pragma unroll
    for (int c = 0; c < 27; ++c) {
        int r = (int)((ri[c >> 2] >> ((c & 3) * 8)) & 255u)
              + ((c & 1) ? (fi[c >> 1] >> 10) : (fi[c >> 1] & 1023));
        if (r < KNN) {
            int oz = c / 9, rem = c - 9 * oz, oy = rem / 3, ox = rem - 3 * oy; // compile-time
            svf[tid * 12 + r] = s_anat[center + (oz - 1) * HXY + (oy - 1) * HX + (ox - 1)];
            scb[tid * 12 + r] = (unsigned char)c;
        }
    }
    __syncthreads();

    // Coalesced copy-out: 16 (lz,ly) lines x 48 float4 per line.
    for (int q = tid; q < 768; q += 256) {
        int line = q / 48, off = q - line * 48;
        int llz = line >> 2, lly = line & 3;
        int vox = ((z0 + llz) << 14) | ((y0 + lly) << 7) | x0;
        g_val4[vox * 3 + off]   = s_val[q];
        g_code32[vox * 3 + off] = s_code[q];
    }
}

// ---------------------------------------------------------------------------
// Pass 2: load the 648-row g_val halo into smem once (coalesced); every
// neighbor row is then 3 LDS.128 at a table-looked-up offset.
// Output staged through smem, written back as float4 (coalesced).
// ---------------------------------------------------------------------------
__global__ __launch_bounds__(256) void pass2_kernel(const float* __restrict__ ksig,
                                                    float* __restrict__ out) {
    __shared__ float4 s_row[HROWS * 3];   // 31104 B, reused for out staging
    __shared__ int    s_tab[27];

    int tid = threadIdx.x;
    int lx = tid & 15, ly = (tid >> 4) & 3, lz = tid >> 6;
    int x0 = blockIdx.x * TX, y0 = blockIdx.y * TY, z0 = blockIdx.z * TZ;

    if (tid < 27) {
        int oz = tid / 9, rem = tid - 9 * oz, oy = rem / 3, ox = rem - 3 * oy;
        s_tab[tid] = (oz - 1) * HXY + (oy - 1) * HX + (ox - 1);
    }

    for (int t = tid; t < HROWS * 3; t += 256) {
        int row = t / 3, comp = t - row * 3;
        int hx = row % HX; int r = row / HX; int hy = r % HY; int hz = r / HY;
        int gx = (x0 + hx + 127) & 127;
        int gy = (y0 + hy + 127) & 127;
        int gz = (z0 + hz + 63) & 63;
        int vox = (gz << 14) | (gy << 7) | gx;
        s_row[t] = g_val4[vox * 3 + comp];
    }

    int i = ((z0 + lz) << 14) | ((y0 + ly) << 7) | (x0 + lx);
    unsigned int cw[3];
    cw[0] = g_code32[i * 3];
    cw[1] = g_code32[i * 3 + 1];
    cw[2] = g_code32[i * 3 + 2];
    float ks = __ldg(&ksig[0]);
    __syncthreads();

    int center = (lz + 1) * HXY + (ly + 1) * HX + (lx + 1);
    float4 a0 = s_row[center * 3], a1 = s_row[center * 3 + 1], a2 = s_row[center * 3 + 2];
    float wi[KNN] = { a0.x, a0.y, a0.z, a0.w, a1.x, a1.y, a1.z, a1.w, a2.x };

    // sigma = std(Wk, ddof=1), two-pass for fp32 stability
    float sum = 0.f;
#pragma unroll
    for (int t = 0; t < KNN; ++t) sum += wi[t];
    float mean = sum * (1.0f / 9.0f);
    float var = 0.f;
#pragma unroll
    for (int t = 0; t < KNN; ++t) { float d = wi[t] - mean; var += d * d; }
    var *= (1.0f / 8.0f);
    float sigma = sqrtf(var);
    bool  zeroSig = (sigma == 0.0f);
    float sig = zeroSig ? 1.0f : sigma;

    // logits = -(||diff|| / sigma / (sqrt(2)*ks))^2 = -s / (2*sigma^2*ks^2)
    float inv = 1.0f / (2.0f * sig * sig * ks * ks);

    float wie[KNN];
#pragma unroll
    for (int t = 0; t < KNN; ++t) wie[t] = wi[t] + 1e-6f;

    float logits[KNN];
#pragma unroll
    for (int j = 0; j < KNN; ++j) {
        int c = (int)((cw[j >> 2] >> ((j & 3) * 8)) & 0xff);
        int rowc = center + s_tab[c];
        float4 b0 = s_row[rowc * 3], b1 = s_row[rowc * 3 + 1], b2 = s_row[rowc * 3 + 2];
        float wn[KNN] = { b0.x, b0.y, b0.z, b0.w, b1.x, b1.y, b1.z, b1.w, b2.x };
        float s = 0.f;
#pragma unroll
        for (int t = 0; t < KNN; ++t) {
            float df = wie[t] - wn[t];
            s = fmaf(df, df, s);
        }
        logits[j] = zeroSig ? 0.0f : -(s * inv);
    }

    // softmax over the 9 neighbors
    float mx = logits[0];
#pragma unroll
    for (int j = 1; j < KNN; ++j) mx = fmaxf(mx, logits[j]);
    float e[KNN], se = 0.f;
#pragma unroll
    for (int j = 0; j < KNN; ++j) { e[j] = __expf(logits[j] - mx); se += e[j]; }
    float rse = 1.0f / se;

    __syncthreads();                       // all halo reads done; reuse buffer
    float* s_outf = (float*)s_row;
#pragma unroll
    for (int j = 0; j < KNN; ++j) s_outf[tid * KNN + j] = e[j] * rse;
    __syncthreads();

    // Coalesced out: 16 lines x 144 floats = 36 float4 per line, 576 total.
    float4* s_out4 = (float4*)s_row;
    for (int q = tid; q < 576; q += 256) {
        int line = q / 36, off = q - line * 36;
        int llz = line >> 2, lly = line & 3;
        int vox = ((z0 + llz) << 14) | ((y0 + lly) << 7) | x0;
        ((float4*)(out + (size_t)vox * KNN))[off] = s_out4[q];
    }
}

extern "C" void kernel_launch(void* const* d_in, const int* in_sizes, int n_in,
                              void* d_out, int out_size) {
    const float* anat = (const float*)d_in[0];
    const float* ksig = (const float*)d_in[1];
    float* out = (float*)d_out;

    dim3 grid(128 / TX, 128 / TY, 64 / TZ);   // 8 x 32 x 16 = 4096 blocks
    pass1_kernel<<<grid, 256>>>(anat);
    pass2_kernel<<<grid, 256>>>(ksig, out);
}

// round 6
// speedup vs baseline: 1.0438x; 1.0438x over previous
#include <cuda_runtime.h>

// Problem constants: H=64, M=N=128, k=9, w=3
#define PTOT (64 * 128 * 128)
#define KNN  9

// Tile: 16 x 4 x 4 voxels per block; halo 18 x 6 x 6
#define TX 16
#define TY 4
#define TZ 4
#define HX 18
#define HY 6
#define HZH 6
#define HROWS (HX * HY * HZH)   // 648
#define HXY (HX * HY)           // 108

// Scratch: per-voxel 9 selected values (12-float padded row, as 3 float4)
// and 9 window codes (bytes packed in 3 u32 words).
__device__ float4       g_val4[PTOT * 3];    // 50.3 MB
__device__ unsigned int g_code32[PTOT * 3];  // 12.6 MB

// ---------------------------------------------------------------------------
// Pass 1: stable top-9 of 27 periodic window neighbors by |v - center|.
//   rank(c) = #{j<c: d_j <= d_c} + #{j>c: d_j < d_c}
// One compare per unordered pair, split between FSETP (FMA pipe) and
// ISETP-on-abs-bits (ALU pipe; identical order for d >= 0).
// Candidate 13 (the center, d=0) is folded out:
//   - pairs (13, c>13): d_13 <= d_c always -> rank_c += 1, folded into the
//     compile-time init of the packed counters (zero instructions);
//   - pairs (j<13, 13): d_j <= 0 <=> bits(d_j)==0 -> cheap integer eq-compare.
// Packed rank counters: 4 bytes per int reg, 2 fields (1 / 1024) per float reg.
// ---------------------------------------------------------------------------
__global__ __launch_bounds__(256) void pass1_kernel(const float* __restrict__ anat) {
    __shared__ float        s_anat[HROWS];
    __shared__ float4       s_val[256 * 3];
    __shared__ unsigned int s_code[256 * 3];

    int tid = threadIdx.x;
    int lx = tid & 15, ly = (tid >> 4) & 3, lz = tid >> 6;
    int x0 = blockIdx.x * TX, y0 = blockIdx.y * TY, z0 = blockIdx.z * TZ;

    for (int t = tid; t < HROWS; t += 256) {
        int hx = t % HX; int r = t / HX; int hy = r % HY; int hz = r / HY;
        int gx = (x0 + hx + 127) & 127;
        int gy = (y0 + hy + 127) & 127;
        int gz = (z0 + hz + 63) & 63;
        s_anat[t] = __ldg(&anat[(gz << 14) | (gy << 7) | gx]);
    }
    __syncthreads();

    int center = (lz + 1) * HXY + (ly + 1) * HX + (lx + 1);
    float ac = s_anat[center];

    float fd[27];
#pragma unroll
    for (int oz = 0; oz < 3; ++oz)
#pragma unroll
        for (int oy = 0; oy < 3; ++oy)
#pragma unroll
            for (int ox = 0; ox < 3; ++ox) {
                int c = oz * 9 + oy * 3 + ox;
                fd[c] = fabsf(s_anat[center + (oz - 1) * HXY + (oy - 1) * HX + (ox - 1)] - ac);
            }

    // Counter init encodes rank_c += 1 for all c > 13 (pairs with center).
    unsigned ri[7] = { 0u, 0u, 0u, 0x01010000u, 0x01010101u, 0x01010101u, 0x00010101u };
    float    rf[14];
#pragma unroll
    for (int k = 0; k < 14; ++k) rf[k] = 0.0f;

    // Pairs (j<13, c=13): d_j == 0 ?
#pragma unroll
    for (int j = 0; j < 13; ++j) {
        if (__float_as_uint(fd[j]) == 0u)
            ri[3] += (1u << 8);                 // rank_13 byte slot
        else
            ri[j >> 2] += (1u << ((j & 3) * 8));
    }

    // All remaining pairs (both endpoints != 13), diagonal order.
#pragma unroll
    for (int o = 1; o < 27; ++o)
#pragma unroll
        for (int j = 0; j + o < 27; ++j) {
            const int c = j + o;
            if (j == 13 || c == 13) continue;
            if (j & 1) {
                // int view of non-negative float: identical ordering (ALU pipe)
                if (__float_as_uint(fd[j]) <= __float_as_uint(fd[c]))
                    ri[c >> 2] += (1u << ((c & 3) * 8));
                else
                    ri[j >> 2] += (1u << ((j & 3) * 8));
            } else {
                // float compare (FMA pipe)
                if (fd[j] <= fd[c])
                    rf[c >> 1] += ((c & 1) ? 1024.0f : 1.0f);
                else
                    rf[j >> 1] += ((j & 1) ? 1024.0f : 1.0f);
            }
        }

    int fi[14];
#pragma unroll
    for (int k = 0; k < 14; ++k) fi[k] = (int)rf[k];

    float*         svf = (float*)s_val;
    unsigned char* scb = (unsigned char*)s_code;
#pragma unroll
    for (int c = 0; c < 27; ++c) {
        int r = (int)((ri[c >> 2] >> ((c & 3) * 8)) & 255u)
              + ((c & 1) ? (fi[c >> 1] >> 10) : (fi[c >> 1] & 1023));
        if (r < KNN) {
            int oz = c / 9, rem = c - 9 * oz, oy = rem / 3, ox = rem - 3 * oy; // compile-time
            svf[tid * 12 + r] = s_anat[center + (oz - 1) * HXY + (oy - 1) * HX + (ox - 1)];
            scb[tid * 12 + r] = (unsigned char)c;
        }
    }
    __syncthreads();

    // Coalesced copy-out: 16 (lz,ly) lines x 48 float4 per line.
    for (int q = tid; q < 768; q += 256) {
        int line = q / 48, off = q - line * 48;
        int llz = line >> 2, lly = line & 3;
        int vox = ((z0 + llz) << 14) | ((y0 + lly) << 7) | x0;
        g_val4[vox * 3 + off]   = s_val[q];
        g_code32[vox * 3 + off] = s_code[q];
    }
}

// ---------------------------------------------------------------------------
// Pass 2: g_val halo staged in smem with 64B row stride + XOR chunk swizzle
// (chunk' = k ^ (row & 3)) -> near-conflict-free LDS.128 row reads
// (48B-stride AoS was a systematic 4-way conflict: banks lane*12 mod 32).
// Output staged through smem (buffer reused), written back as float4.
// ---------------------------------------------------------------------------
#define SROW(row, k) (((row) << 2) + ((k) ^ ((row) & 3)))

__global__ __launch_bounds__(256) void pass2_kernel(const float* __restrict__ ksig,
                                                    float* __restrict__ out) {
    __shared__ float4 s_row[HROWS * 4];   // 41472 B, reused for out staging
    __shared__ int    s_tab[27];

    int tid = threadIdx.x;
    int lx = tid & 15, ly = (tid >> 4) & 3, lz = tid >> 6;
    int x0 = blockIdx.x * TX, y0 = blockIdx.y * TY, z0 = blockIdx.z * TZ;

    if (tid < 27) {
        int oz = tid / 9, rem = tid - 9 * oz, oy = rem / 3, ox = rem - 3 * oy;
        s_tab[tid] = (oz - 1) * HXY + (oy - 1) * HX + (ox - 1);
    }

    for (int t = tid; t < HROWS * 3; t += 256) {
        int row = t / 3, k = t - row * 3;
        int hx = row % HX; int r = row / HX; int hy = r % HY; int hz = r / HY;
        int gx = (x0 + hx + 127) & 127;
        int gy = (y0 + hy + 127) & 127;
        int gz = (z0 + hz + 63) & 63;
        int vox = (gz << 14) | (gy << 7) | gx;
        s_row[SROW(row, k)] = g_val4[vox * 3 + k];
    }

    int i = ((z0 + lz) << 14) | ((y0 + ly) << 7) | (x0 + lx);
    unsigned int cw[3];
    cw[0] = g_code32[i * 3];
    cw[1] = g_code32[i * 3 + 1];
    cw[2] = g_code32[i * 3 + 2];
    float ks = __ldg(&ksig[0]);
    __syncthreads();

    int center = (lz + 1) * HXY + (ly + 1) * HX + (lx + 1);
    float4 a0 = s_row[SROW(center, 0)];
    float4 a1 = s_row[SROW(center, 1)];
    float4 a2 = s_row[SROW(center, 2)];
    float wi[KNN] = { a0.x, a0.y, a0.z, a0.w, a1.x, a1.y, a1.z, a1.w, a2.x };

    // sigma = std(Wk, ddof=1), two-pass for fp32 stability
    float sum = 0.f;
#pragma unroll
    for (int t = 0; t < KNN; ++t) sum += wi[t];
    float mean = sum * (1.0f / 9.0f);
    float var = 0.f;
#pragma unroll
    for (int t = 0; t < KNN; ++t) { float d = wi[t] - mean; var += d * d; }
    var *= (1.0f / 8.0f);
    float sigma = sqrtf(var);
    bool  zeroSig = (sigma == 0.0f);
    float sig = zeroSig ? 1.0f : sigma;

    // logits = -(||diff|| / sigma / (sqrt(2)*ks))^2 = -s / (2*sigma^2*ks^2)
    float inv = 1.0f / (2.0f * sig * sig * ks * ks);

    float wie[KNN];
#pragma unroll
    for (int t = 0; t < KNN; ++t) wie[t] = wi[t] + 1e-6f;

    float logits[KNN];
#pragma unroll
    for (int j = 0; j < KNN; ++j) {
        int c = (int)((cw[j >> 2] >> ((j & 3) * 8)) & 0xff);
        int rowc = center + s_tab[c];
        float4 b0 = s_row[SROW(rowc, 0)];
        float4 b1 = s_row[SROW(rowc, 1)];
        float4 b2 = s_row[SROW(rowc, 2)];
        float wn[KNN] = { b0.x, b0.y, b0.z, b0.w, b1.x, b1.y, b1.z, b1.w, b2.x };
        float s = 0.f;
#pragma unroll
        for (int t = 0; t < KNN; ++t) {
            float df = wie[t] - wn[t];
            s = fmaf(df, df, s);
        }
        logits[j] = zeroSig ? 0.0f : -(s * inv);
    }

    // softmax over the 9 neighbors
    float mx = logits[0];
#pragma unroll
    for (int j = 1; j < KNN; ++j) mx = fmaxf(mx, logits[j]);
    float e[KNN], se = 0.f;
#pragma unroll
    for (int j = 0; j < KNN; ++j) { e[j] = __expf(logits[j] - mx); se += e[j]; }
    float rse = 1.0f / se;

    __syncthreads();                       // all halo reads done; reuse buffer
    float* s_outf = (float*)s_row;
#pragma unroll
    for (int j = 0; j < KNN; ++j) s_outf[tid * KNN + j] = e[j] * rse;
    __syncthreads();

    // Coalesced out: 16 lines x 144 floats = 36 float4 per line, 576 total.
    float4* s_out4 = (float4*)s_row;
    for (int q = tid; q < 576; q += 256) {
        int line = q / 36, off = q - line * 36;
        int llz = line >> 2, lly = line & 3;
        int vox = ((z0 + llz) << 14) | ((y0 + lly) << 7) | x0;
        ((float4*)(out + (size_t)vox * KNN))[off] = s_out4[q];
    }
}

extern "C" void kernel_launch(void* const* d_in, const int* in_sizes, int n_in,
                              void* d_out, int out_size) {
    const float* anat = (const float*)d_in[0];
    const float* ksig = (const float*)d_in[1];
    float* out = (float*)d_out;

    dim3 grid(128 / TX, 128 / TY, 64 / TZ);   // 8 x 32 x 16 = 4096 blocks
    pass1_kernel<<<grid, 256>>>(anat);
    pass2_kernel<<<grid, 256>>>(ksig, out);
}

// round 7
// speedup vs baseline: 1.1600x; 1.1113x over previous
#include <cuda_runtime.h>

// Problem constants: H=64, M=N=128, k=9, w=3
#define PTOT (64 * 128 * 128)
#define KNN  9

// Tile: 16 x 4 x 4 voxels per block; halo 18 x 6 x 6
#define TX 16
#define TY 4
#define TZ 4
#define HX 18
#define HY 6
#define HZH 6
#define HROWS (HX * HY * HZH)   // 648
#define HXY (HX * HY)           // 108

// Scratch: per-voxel 9 selected values (12-float padded row, as 3 float4)
// and 9 window codes (bytes packed in 3 u32 words).
__device__ float4       g_val4[PTOT * 3];    // 50.3 MB
__device__ unsigned int g_code32[PTOT * 3];  // 12.6 MB

// ---------------------------------------------------------------------------
// Pass 1 (unchanged from R6 — measured 72.3us): stable top-9 of 27 periodic
// window neighbors by |v - center|.
//   rank(c) = #{j<c: d_j <= d_c} + #{j>c: d_j < d_c}
// One compare per unordered pair, split between FSETP (FMA pipe) and
// ISETP-on-abs-bits (ALU pipe; identical order for d >= 0), with the center
// candidate (13, d=0) algebraically folded into the counter init.
// ---------------------------------------------------------------------------
__global__ __launch_bounds__(256) void pass1_kernel(const float* __restrict__ anat) {
    __shared__ float        s_anat[HROWS];
    __shared__ float4       s_val[256 * 3];
    __shared__ unsigned int s_code[256 * 3];

    int tid = threadIdx.x;
    int lx = tid & 15, ly = (tid >> 4) & 3, lz = tid >> 6;
    int x0 = blockIdx.x * TX, y0 = blockIdx.y * TY, z0 = blockIdx.z * TZ;

    for (int t = tid; t < HROWS; t += 256) {
        int hx = t % HX; int r = t / HX; int hy = r % HY; int hz = r / HY;
        int gx = (x0 + hx + 127) & 127;
        int gy = (y0 + hy + 127) & 127;
        int gz = (z0 + hz + 63) & 63;
        s_anat[t] = __ldg(&anat[(gz << 14) | (gy << 7) | gx]);
    }
    __syncthreads();

    int center = (lz + 1) * HXY + (ly + 1) * HX + (lx + 1);
    float ac = s_anat[center];

    float fd[27];
#pragma unroll
    for (int oz = 0; oz < 3; ++oz)
#pragma unroll
        for (int oy = 0; oy < 3; ++oy)
#pragma unroll
            for (int ox = 0; ox < 3; ++ox) {
                int c = oz * 9 + oy * 3 + ox;
                fd[c] = fabsf(s_anat[center + (oz - 1) * HXY + (oy - 1) * HX + (ox - 1)] - ac);
            }

    // Counter init encodes rank_c += 1 for all c > 13 (pairs with center).
    unsigned ri[7] = { 0u, 0u, 0u, 0x01010000u, 0x01010101u, 0x01010101u, 0x00010101u };
    float    rf[14];
#pragma unroll
    for (int k = 0; k < 14; ++k) rf[k] = 0.0f;

    // Pairs (j<13, c=13): d_j == 0 ?
#pragma unroll
    for (int j = 0; j < 13; ++j) {
        if (__float_as_uint(fd[j]) == 0u)
            ri[3] += (1u << 8);                 // rank_13 byte slot
        else
            ri[j >> 2] += (1u << ((j & 3) * 8));
    }

    // All remaining pairs (both endpoints != 13), diagonal order.
#pragma unroll
    for (int o = 1; o < 27; ++o)
#pragma unroll
        for (int j = 0; j + o < 27; ++j) {
            const int c = j + o;
            if (j == 13 || c == 13) continue;
            if (j & 1) {
                // int view of non-negative float: identical ordering (ALU pipe)
                if (__float_as_uint(fd[j]) <= __float_as_uint(fd[c]))
                    ri[c >> 2] += (1u << ((c & 3) * 8));
                else
                    ri[j >> 2] += (1u << ((j & 3) * 8));
            } else {
                // float compare (FMA pipe)
                if (fd[j] <= fd[c])
                    rf[c >> 1] += ((c & 1) ? 1024.0f : 1.0f);
                else
                    rf[j >> 1] += ((j & 1) ? 1024.0f : 1.0f);
            }
        }

    int fi[14];
#pragma unroll
    for (int k = 0; k < 14; ++k) fi[k] = (int)rf[k];

    float*         svf = (float*)s_val;
    unsigned char* scb = (unsigned char*)s_code;
#pragma unroll
    for (int c = 0; c < 27; ++c) {
        int r = (int)((ri[c >> 2] >> ((c & 3) * 8)) & 255u)
              + ((c & 1) ? (fi[c >> 1] >> 10) : (fi[c >> 1] & 1023));
        if (r < KNN) {
            int oz = c / 9, rem = c - 9 * oz, oy = rem / 3, ox = rem - 3 * oy; // compile-time
            svf[tid * 12 + r] = s_anat[center + (oz - 1) * HXY + (oy - 1) * HX + (ox - 1)];
            scb[tid * 12 + r] = (unsigned char)c;
        }
    }
    __syncthreads();

    // Coalesced copy-out: 16 (lz,ly) lines x 48 float4 per line.
    for (int q = tid; q < 768; q += 256) {
        int line = q / 48, off = q - line * 48;
        int llz = line >> 2, lly = line & 3;
        int vox = ((z0 + llz) << 14) | ((y0 + lly) << 7) | x0;
        g_val4[vox * 3 + off]   = s_val[q];
        g_code32[vox * 3 + off] = s_code[q];
    }
}

// ---------------------------------------------------------------------------
// Pass 2: halo of 648 g_val rows staged in smem at SCALAR stride 9 floats
// (gcd(9,32)=1): LDS.32 row reads conflict only when data-dependent rows are
// congruent mod 32 (rare), vs mod 8 for float4 reads. 23 KB smem.
// Output staged through the same buffer, written back as float4.
// ---------------------------------------------------------------------------
__global__ __launch_bounds__(256) void pass2_kernel(const float* __restrict__ ksig,
                                                    float* __restrict__ out) {
    __shared__ __align__(16) float s9[HROWS * 9];   // 23328 B, reused for out staging
    __shared__ int s_tab[27];

    int tid = threadIdx.x;
    int lx = tid & 15, ly = (tid >> 4) & 3, lz = tid >> 6;
    int x0 = blockIdx.x * TX, y0 = blockIdx.y * TY, z0 = blockIdx.z * TZ;

    if (tid < 27) {
        int oz = tid / 9, rem = tid - 9 * oz, oy = rem / 3, ox = rem - 3 * oy;
        s_tab[tid] = (oz - 1) * HXY + (oy - 1) * HX + (ox - 1);
    }

    // Halo load: one row per thread per iteration. Global reads are 48B/thread
    // over consecutive rows (fully coalesced); smem writes stride 9 per lane
    // (conflict-free per component).
    for (int row = tid; row < HROWS; row += 256) {
        int hx = row % HX; int r = row / HX; int hy = r % HY; int hz = r / HY;
        int gx = (x0 + hx + 127) & 127;
        int gy = (y0 + hy + 127) & 127;
        int gz = (z0 + hz + 63) & 63;
        int vox = (gz << 14) | (gy << 7) | gx;
        float4 b0 = g_val4[vox * 3];
        float4 b1 = g_val4[vox * 3 + 1];
        float4 b2 = g_val4[vox * 3 + 2];
        float* d = &s9[row * 9];
        d[0] = b0.x; d[1] = b0.y; d[2] = b0.z; d[3] = b0.w;
        d[4] = b1.x; d[5] = b1.y; d[6] = b1.z; d[7] = b1.w;
        d[8] = b2.x;
    }

    int i = ((z0 + lz) << 14) | ((y0 + ly) << 7) | (x0 + lx);
    unsigned int cw[3];
    cw[0] = g_code32[i * 3];
    cw[1] = g_code32[i * 3 + 1];
    cw[2] = g_code32[i * 3 + 2];
    float ks = __ldg(&ksig[0]);
    __syncthreads();

    int center = (lz + 1) * HXY + (ly + 1) * HX + (lx + 1);
    float wi[KNN];
#pragma unroll
    for (int t = 0; t < KNN; ++t) wi[t] = s9[center * 9 + t];

    // sigma = std(Wk, ddof=1), two-pass for fp32 stability
    float sum = 0.f;
#pragma unroll
    for (int t = 0; t < KNN; ++t) sum += wi[t];
    float mean = sum * (1.0f / 9.0f);
    float var = 0.f;
#pragma unroll
    for (int t = 0; t < KNN; ++t) { float d = wi[t] - mean; var += d * d; }
    var *= (1.0f / 8.0f);
    float sigma = sqrtf(var);
    bool  zeroSig = (sigma == 0.0f);
    float sig = zeroSig ? 1.0f : sigma;

    // logits = -(||diff|| / sigma / (sqrt(2)*ks))^2 = -s / (2*sigma^2*ks^2)
    float inv = 1.0f / (2.0f * sig * sig * ks * ks);

    float wie[KNN];
#pragma unroll
    for (int t = 0; t < KNN; ++t) wie[t] = wi[t] + 1e-6f;

    float logits[KNN];
#pragma unroll
    for (int j = 0; j < KNN; ++j) {
        int c = (int)((cw[j >> 2] >> ((j & 3) * 8)) & 0xff);
        const float* nr = &s9[(center + s_tab[c]) * 9];
        float s = 0.f;
#pragma unroll
        for (int t = 0; t < KNN; ++t) {
            float df = wie[t] - nr[t];
            s = fmaf(df, df, s);
        }
        logits[j] = zeroSig ? 0.0f : -(s * inv);
    }

    // softmax over the 9 neighbors
    float mx = logits[0];
#pragma unroll
    for (int j = 1; j < KNN; ++j) mx = fmaxf(mx, logits[j]);
    float e[KNN], se = 0.f;
#pragma unroll
    for (int j = 0; j < KNN; ++j) { e[j] = __expf(logits[j] - mx); se += e[j]; }
    float rse = 1.0f / se;

    __syncthreads();                       // all halo reads done; reuse buffer
#pragma unroll
    for (int j = 0; j < KNN; ++j) s9[tid * KNN + j] = e[j] * rse;
    __syncthreads();

    // Coalesced out: 16 lines x 144 floats = 36 float4 per line, 576 total.
    float4* s_out4 = (float4*)s9;
    for (int q = tid; q < 576; q += 256) {
        int line = q / 36, off = q - line * 36;
        int llz = line >> 2, lly = line & 3;
        int vox = ((z0 + llz) << 14) | ((y0 + lly) << 7) | x0;
        ((float4*)(out + (size_t)vox * KNN))[off] = s_out4[q];
    }
}

extern "C" void kernel_launch(void* const* d_in, const int* in_sizes, int n_in,
                              void* d_out, int out_size) {
    const float* anat = (const float*)d_in[0];
    const float* ksig = (const float*)d_in[1];
    float* out = (float*)d_out;

    dim3 grid(128 / TX, 128 / TY, 64 / TZ);   // 8 x 32 x 16 = 4096 blocks
    pass1_kernel<<<grid, 256>>>(anat);
    pass2_kernel<<<grid, 256>>>(ksig, out);
}